// round 16
// baseline (speedup 1.0000x reference)
#include <cuda_runtime.h>

#define NUM_EDGES   500000
#define SIZE1       80000
#define SIZE2       80000
#define BATCH       8

// Batch-minor copy of x: xt[s*8 + b]. 2.56 MB, L2-resident during edge kernel.
__device__ float g_xt[SIZE1 * BATCH];

// Quad-packed accumulator scratch, 2 copies (edge parity).
// q[copy][p][s][c] : p = b>>2, c = b&3.  (round-13 layout — measured best)
#define QPLANE  (SIZE2 * 4)
#define QCOPY   (2 * QPLANE)
__device__ float g_q[2 * QCOPY];

// ---------------------------------------------------------------------------
// K1 (prep): zero scratch (float4); transpose x[b,s] -> xt[s,b].
// ---------------------------------------------------------------------------
__global__ void __launch_bounds__(256)
prep_kernel(const float* __restrict__ x) {
    int idx = blockIdx.x * blockDim.x + threadIdx.x;

    if (idx < (2 * QCOPY) / 4) {
        reinterpret_cast<float4*>(g_q)[idx] = make_float4(0.f, 0.f, 0.f, 0.f);
    }

    if (idx < SIZE1 * 2) {
        int s = idx >> 1;
        int h = idx & 1;           // batch half: 0 -> b=0..3, 1 -> b=4..7
        float4 v;
        v.x = __ldg(&x[(4 * h + 0) * SIZE1 + s]);
        v.y = __ldg(&x[(4 * h + 1) * SIZE1 + s]);
        v.z = __ldg(&x[(4 * h + 2) * SIZE1 + s]);
        v.w = __ldg(&x[(4 * h + 3) * SIZE1 + s]);
        *reinterpret_cast<float4*>(g_xt + (size_t)s * 8 + 4 * h) = v;
    }
}

// ---------------------------------------------------------------------------
// K2: edge kernel. 4 lanes per edge, 8 edges per warp. Lane (g, t).
//  - v row i=t via dense cooperative weight load (512B/instr)
//  - x: lane t loads row i=t of the edge's 128B block as 2 float4
//    (2 line-touches/edge), then one 4x4 float2 butterfly transpose
//    recovers x[i][2t,2t+1]
//  - accumulate all j for batches 2t,2t+1 via shfl of v rows
//  - round-13 output path: pair swap + 2 red.v4 into quad-packed scratch
//    (plane p = t>>1, rows dst4+2h, dst4+2h+1) — 4 red line-touches/edge
// ---------------------------------------------------------------------------
__global__ void __launch_bounds__(256)
spmm_edge_kernel(const float4* __restrict__ w_mean4,
                 const float4* __restrict__ w_lv4,
                 const float4* __restrict__ eps_w4,
                 const int* __restrict__ rows,
                 const int* __restrict__ cols) {
    const unsigned FULL = 0xffffffffu;
    int lane = threadIdx.x & 31;
    int warp = (blockIdx.x * blockDim.x + threadIdx.x) >> 5;
    int e0 = warp * 8;
    if (e0 >= NUM_EDGES) return;       // NUM_EDGES % 8 == 0

    const int t = lane & 3;
    const int g = lane >> 2;
    const int gbase = lane & ~3;
    const bool t0 = (t & 1) != 0;
    const bool t1 = (t & 2) != 0;
    const int h = t & 1;               // j-half
    const int p = t >> 1;              // quad plane

    // Dense weight loads: addr = e0*64B + lane*16B, contiguous 512B per instr.
    float4 m  = __ldg(&w_mean4[(size_t)e0 * 4 + lane]);
    float4 lv = __ldg(&w_lv4 [(size_t)e0 * 4 + lane]);
    float4 ep = __ldg(&eps_w4[(size_t)e0 * 4 + lane]);
    float4 vo;                          // v row i=t of edge e0+g (across j)
    vo.x = fmaf(ep.x, __expf(lv.x), m.x);
    vo.y = fmaf(ep.y, __expf(lv.y), m.y);
    vo.z = fmaf(ep.z, __expf(lv.z), m.z);
    vo.w = fmaf(ep.w, __expf(lv.w), m.w);

    // Indices: lanes 0-7 load rows (dst*4), lanes 8-15 load cols (src*4).
    int idxv = 0;
    if (lane < 8)       idxv = __ldg(&rows[(size_t)(e0 + lane) * 16]);
    else if (lane < 16) idxv = __ldg(&cols[(size_t)(e0 + lane - 8) * 16]);
    int dst4 = __shfl_sync(FULL, idxv, g);
    int src4 = __shfl_sync(FULL, idxv, 8 + g);

    // x row i=t of this edge's block: 2 float4 (same 128B line).
    const float4* xr = reinterpret_cast<const float4*>(g_xt + (size_t)(src4 + t) * 8);
    float4 xr0 = __ldg(&xr[0]);     // batches 0-3 of row t
    float4 xr1 = __ldg(&xr[1]);     // batches 4-7 of row t

    // X[c] = x[row t][b=2c,2c+1]
    float2 X0 = make_float2(xr0.x, xr0.y);
    float2 X1 = make_float2(xr0.z, xr0.w);
    float2 X2 = make_float2(xr1.x, xr1.y);
    float2 X3 = make_float2(xr1.z, xr1.w);

    // Butterfly transpose within 4-lane group: lane t wants x[i][2t,2t+1].
    float2 Xo = t1 ? (t0 ? X3 : X2) : (t0 ? X1 : X0);   // X[t]
    float2 s1 = t0 ? (t1 ? X2 : X0) : (t1 ? X3 : X1);   // X[t^1]
    float2 s2 = t1 ? (t0 ? X1 : X0) : (t0 ? X3 : X2);   // X[t^2]
    float2 s3 = t0 ? (t1 ? X0 : X2) : (t1 ? X1 : X3);   // X[t^3]
    float2 r1, r2, r3;
    r1.x = __shfl_xor_sync(FULL, s1.x, 1); r1.y = __shfl_xor_sync(FULL, s1.y, 1);
    r2.x = __shfl_xor_sync(FULL, s2.x, 2); r2.y = __shfl_xor_sync(FULL, s2.y, 2);
    r3.x = __shfl_xor_sync(FULL, s3.x, 3); r3.y = __shfl_xor_sync(FULL, s3.y, 3);

    // acc[j*2 + bb]: output j = 0..3 for batches 2t+bb.
    float acc[8];
#pragma unroll
    for (int k = 0; k < 8; k++) acc[k] = 0.0f;

#pragma unroll
    for (int i = 0; i < 4; i++) {
        int k = t ^ i;
        float2 xvi = (k == 0) ? Xo : (k == 1) ? r1 : (k == 2) ? r2 : r3;  // x[i][2t,2t+1]
        float vix = __shfl_sync(FULL, vo.x, gbase + i);   // v[i][0]
        float viy = __shfl_sync(FULL, vo.y, gbase + i);   // v[i][1]
        float viz = __shfl_sync(FULL, vo.z, gbase + i);   // v[i][2]
        float viw = __shfl_sync(FULL, vo.w, gbase + i);   // v[i][3]
        acc[0] = fmaf(vix, xvi.x, acc[0]);
        acc[1] = fmaf(vix, xvi.y, acc[1]);
        acc[2] = fmaf(viy, xvi.x, acc[2]);
        acc[3] = fmaf(viy, xvi.y, acc[3]);
        acc[4] = fmaf(viz, xvi.x, acc[4]);
        acc[5] = fmaf(viz, xvi.y, acc[5]);
        acc[6] = fmaf(viw, xvi.x, acc[6]);
        acc[7] = fmaf(viw, xvi.y, acc[7]);
    }

    // Round-13 output path: pair swap (xor 1) so each lane emits (c0..c3)
    // vectors for j = 2h, 2h+1 into plane p.
    float s0f = h ? acc[0] : acc[4];
    float s1f = h ? acc[1] : acc[5];
    float s2f = h ? acc[2] : acc[6];
    float s3f = h ? acc[3] : acc[7];
    float q0 = __shfl_xor_sync(FULL, s0f, 1);
    float q1 = __shfl_xor_sync(FULL, s1f, 1);
    float q2 = __shfl_xor_sync(FULL, s2f, 1);
    float q3 = __shfl_xor_sync(FULL, s3f, 1);

    float a0x = h ? q0 : acc[0];
    float a0y = h ? q1 : acc[1];
    float a0z = h ? acc[4] : q0;
    float a0w = h ? acc[5] : q1;
    float a1x = h ? q2 : acc[2];
    float a1y = h ? q3 : acc[3];
    float a1z = h ? acc[6] : q2;
    float a1w = h ? acc[7] : q3;

    int e = e0 + g;
    float* qb = g_q + (size_t)(e & 1) * QCOPY + (size_t)p * QPLANE
              + (size_t)(dst4 + 2 * h) * 4;
    asm volatile("red.global.add.v4.f32 [%0], {%1, %2, %3, %4};"
                 :: "l"(qb), "f"(a0x), "f"(a0y), "f"(a0z), "f"(a0w)
                 : "memory");
    asm volatile("red.global.add.v4.f32 [%0], {%1, %2, %3, %4};"
                 :: "l"(qb + 4), "f"(a1x), "f"(a1y), "f"(a1z), "f"(a1w)
                 : "memory");
}

// ---------------------------------------------------------------------------
// K3 (finalize): one thread per node s. Dense float4 reads of both scratch
// copies; bias once; 8 coalesced plane stores. Tail threads zero kl.
// ---------------------------------------------------------------------------
__global__ void __launch_bounds__(256)
finalize_kernel(const float* __restrict__ b_mean,
                const float* __restrict__ b_log_var,
                const float* __restrict__ eps_b,
                float* __restrict__ out, int out_size) {
    int idx = blockIdx.x * blockDim.x + threadIdx.x;
    if (idx < SIZE2) {
        int s = idx;
        // plane p holds (c0..c3) = batches 4p..4p+3 at s*4
        const float4* q0p0 = reinterpret_cast<const float4*>(g_q + (size_t)s * 4);
        const float4* q0p1 = reinterpret_cast<const float4*>(g_q + QPLANE + (size_t)s * 4);
        const float4* q1p0 = reinterpret_cast<const float4*>(g_q + QCOPY + (size_t)s * 4);
        const float4* q1p1 = reinterpret_cast<const float4*>(g_q + QCOPY + QPLANE + (size_t)s * 4);
        float4 lo = *q0p0, hi = *q0p1;
        float4 lo2 = *q1p0, hi2 = *q1p1;
        float bias = fmaf(__ldg(&eps_b[s]), __expf(__ldg(&b_log_var[s])),
                          __ldg(&b_mean[s]));
        out[0 * SIZE2 + s] = lo.x + lo2.x + bias;
        out[1 * SIZE2 + s] = lo.y + lo2.y + bias;
        out[2 * SIZE2 + s] = lo.z + lo2.z + bias;
        out[3 * SIZE2 + s] = lo.w + lo2.w + bias;
        out[4 * SIZE2 + s] = hi.x + hi2.x + bias;
        out[5 * SIZE2 + s] = hi.y + hi2.y + bias;
        out[6 * SIZE2 + s] = hi.z + hi2.z + bias;
        out[7 * SIZE2 + s] = hi.w + hi2.w + bias;
    } else {
        int k = BATCH * SIZE2 + (idx - SIZE2);
        if (k < out_size) out[k] = 0.0f;   // kl = 0
    }
}

extern "C" void kernel_launch(void* const* d_in, const int* in_sizes, int n_in,
                              void* d_out, int out_size) {
    const float* x      = (const float*)d_in[0];
    const float* w_mean = (const float*)d_in[1];
    const float* w_lv   = (const float*)d_in[2];
    const float* b_mean = (const float*)d_in[3];
    const float* b_lv   = (const float*)d_in[4];
    const float* eps_w  = (const float*)d_in[5];
    const float* eps_b  = (const float*)d_in[6];
    const int*   rows   = (const int*)d_in[7];
    const int*   cols   = (const int*)d_in[8];
    float* out = (float*)d_out;

    int prep_n = (2 * QCOPY) / 4;                      // 320k zeroing threads
    if (prep_n < SIZE1 * 2) prep_n = SIZE1 * 2;
    prep_kernel<<<(prep_n + 255) / 256, 256>>>(x);

    spmm_edge_kernel<<<(NUM_EDGES / 8 * 32 + 255) / 256, 256>>>(
        (const float4*)w_mean, (const float4*)w_lv, (const float4*)eps_w,
        rows, cols);

    int fin_n = SIZE2 + 512;                           // nodes + kl tail
    finalize_kernel<<<(fin_n + 255) / 256, 256>>>(b_mean, b_lv, eps_b, out, out_size);
}

// round 17
// speedup vs baseline: 1.0851x; 1.0851x over previous
#include <cuda_runtime.h>

#define NUM_EDGES   500000
#define SIZE1       80000
#define SIZE2       80000
#define BATCH       8

// Batch-minor copy of x: xt[s*8 + b]. 2.56 MB, L2-resident during edge kernel.
__device__ float g_xt[SIZE1 * BATCH];

// Quad-packed accumulator scratch, 2 copies (edge parity).
// q[copy][p][s][c] : p = b>>2, c = b&3.  (round-13 layout — measured best)
// ZERO-RESTORE INVARIANT: zeroed at module load; finalize_kernel re-zeroes
// every line after consuming it, so each kernel_launch call starts from zeros.
#define QPLANE  (SIZE2 * 4)
#define QCOPY   (2 * QPLANE)
__device__ float g_q[2 * QCOPY];

// ---------------------------------------------------------------------------
// K1 (prep): transpose x[b,s] -> xt[s,b] only (no scratch zeroing needed).
// ---------------------------------------------------------------------------
__global__ void __launch_bounds__(256)
prep_kernel(const float* __restrict__ x) {
    int idx = blockIdx.x * blockDim.x + threadIdx.x;
    if (idx < SIZE1 * 2) {
        int s = idx >> 1;
        int h = idx & 1;           // batch half: 0 -> b=0..3, 1 -> b=4..7
        float4 v;
        v.x = __ldg(&x[(4 * h + 0) * SIZE1 + s]);
        v.y = __ldg(&x[(4 * h + 1) * SIZE1 + s]);
        v.z = __ldg(&x[(4 * h + 2) * SIZE1 + s]);
        v.w = __ldg(&x[(4 * h + 3) * SIZE1 + s]);
        *reinterpret_cast<float4*>(g_xt + (size_t)s * 8 + 4 * h) = v;
    }
}

// ---------------------------------------------------------------------------
// K2: edge kernel (round-13 verbatim — measured best edge pass).
// 4 lanes per edge, 8 edges per warp. Lane (g, t): t = 2p + h.
//  - v row i=t via dense cooperative weight load (512B/instr)
//  - x: 4 float2 loads from the edge's 128B xt block
//  - accumulate all j for batches 2t,2t+1 via shfl of v rows
//  - pair swap (xor 1) + 2 red.v4 into quad-packed scratch
// ---------------------------------------------------------------------------
__global__ void __launch_bounds__(256)
spmm_edge_kernel(const float4* __restrict__ w_mean4,
                 const float4* __restrict__ w_lv4,
                 const float4* __restrict__ eps_w4,
                 const int* __restrict__ rows,
                 const int* __restrict__ cols) {
    const unsigned FULL = 0xffffffffu;
    int lane = threadIdx.x & 31;
    int warp = (blockIdx.x * blockDim.x + threadIdx.x) >> 5;
    int e0 = warp * 8;
    if (e0 >= NUM_EDGES) return;       // NUM_EDGES % 8 == 0

    const int t = lane & 3;
    const int g = lane >> 2;
    const int gbase = lane & ~3;
    const int h = t & 1;               // j-half
    const int p = t >> 1;              // quad plane

    // Dense weight loads: addr = e0*64B + lane*16B, contiguous 512B per instr.
    float4 m  = __ldg(&w_mean4[(size_t)e0 * 4 + lane]);
    float4 lv = __ldg(&w_lv4 [(size_t)e0 * 4 + lane]);
    float4 ep = __ldg(&eps_w4[(size_t)e0 * 4 + lane]);
    float4 vo;                          // v row i=t of edge e0+g (across j)
    vo.x = fmaf(ep.x, __expf(lv.x), m.x);
    vo.y = fmaf(ep.y, __expf(lv.y), m.y);
    vo.z = fmaf(ep.z, __expf(lv.z), m.z);
    vo.w = fmaf(ep.w, __expf(lv.w), m.w);

    // Indices: lanes 0-7 load rows (dst*4), lanes 8-15 load cols (src*4).
    int idxv = 0;
    if (lane < 8)       idxv = __ldg(&rows[(size_t)(e0 + lane) * 16]);
    else if (lane < 16) idxv = __ldg(&cols[(size_t)(e0 + lane - 8) * 16]);
    int dst4 = __shfl_sync(FULL, idxv, g);
    int src4 = __shfl_sync(FULL, idxv, 8 + g);

    // x for batches 2t, 2t+1, rows i=0..3 from the 128B block at src4*32B.
    const float* xb = g_xt + (size_t)src4 * 8 + 2 * t;
    float2 xv[4];
#pragma unroll
    for (int i = 0; i < 4; i++)
        xv[i] = *reinterpret_cast<const float2*>(xb + i * 8);

    // acc[j*2 + bb]: output j = 0..3 for batches 2t+bb.
    float acc[8];
#pragma unroll
    for (int k = 0; k < 8; k++) acc[k] = 0.0f;

#pragma unroll
    for (int i = 0; i < 4; i++) {
        float vix = __shfl_sync(FULL, vo.x, gbase + i);   // v[i][0]
        float viy = __shfl_sync(FULL, vo.y, gbase + i);   // v[i][1]
        float viz = __shfl_sync(FULL, vo.z, gbase + i);   // v[i][2]
        float viw = __shfl_sync(FULL, vo.w, gbase + i);   // v[i][3]
        acc[0] = fmaf(vix, xv[i].x, acc[0]);
        acc[1] = fmaf(vix, xv[i].y, acc[1]);
        acc[2] = fmaf(viy, xv[i].x, acc[2]);
        acc[3] = fmaf(viy, xv[i].y, acc[3]);
        acc[4] = fmaf(viz, xv[i].x, acc[4]);
        acc[5] = fmaf(viz, xv[i].y, acc[5]);
        acc[6] = fmaf(viw, xv[i].x, acc[6]);
        acc[7] = fmaf(viw, xv[i].y, acc[7]);
    }

    // Pair swap (xor 1): each lane emits (c0..c3) vectors for j = 2h, 2h+1.
    float s0 = h ? acc[0] : acc[4];
    float s1 = h ? acc[1] : acc[5];
    float s2 = h ? acc[2] : acc[6];
    float s3 = h ? acc[3] : acc[7];
    float r0 = __shfl_xor_sync(FULL, s0, 1);
    float r1 = __shfl_xor_sync(FULL, s1, 1);
    float r2 = __shfl_xor_sync(FULL, s2, 1);
    float r3 = __shfl_xor_sync(FULL, s3, 1);

    float a0x = h ? r0 : acc[0];
    float a0y = h ? r1 : acc[1];
    float a0z = h ? acc[4] : r0;
    float a0w = h ? acc[5] : r1;
    float a1x = h ? r2 : acc[2];
    float a1y = h ? r3 : acc[3];
    float a1z = h ? acc[6] : r2;
    float a1w = h ? acc[7] : r3;

    int e = e0 + g;
    float* qb = g_q + (size_t)(e & 1) * QCOPY + (size_t)p * QPLANE
              + (size_t)(dst4 + 2 * h) * 4;
    asm volatile("red.global.add.v4.f32 [%0], {%1, %2, %3, %4};"
                 :: "l"(qb), "f"(a0x), "f"(a0y), "f"(a0z), "f"(a0w)
                 : "memory");
    asm volatile("red.global.add.v4.f32 [%0], {%1, %2, %3, %4};"
                 :: "l"(qb + 4), "f"(a1x), "f"(a1y), "f"(a1z), "f"(a1w)
                 : "memory");
}

// ---------------------------------------------------------------------------
// K3 (finalize): one thread per node s. Dense float4 reads of both scratch
// copies, then RE-ZERO those lines (restores the invariant for the next
// call); bias once; 8 coalesced plane stores. Tail threads zero kl.
// ---------------------------------------------------------------------------
__global__ void __launch_bounds__(256)
finalize_kernel(const float* __restrict__ b_mean,
                const float* __restrict__ b_log_var,
                const float* __restrict__ eps_b,
                float* __restrict__ out, int out_size) {
    int idx = blockIdx.x * blockDim.x + threadIdx.x;
    if (idx < SIZE2) {
        int s = idx;
        float4* q0p0 = reinterpret_cast<float4*>(g_q + (size_t)s * 4);
        float4* q0p1 = reinterpret_cast<float4*>(g_q + QPLANE + (size_t)s * 4);
        float4* q1p0 = reinterpret_cast<float4*>(g_q + QCOPY + (size_t)s * 4);
        float4* q1p1 = reinterpret_cast<float4*>(g_q + QCOPY + QPLANE + (size_t)s * 4);
        float4 lo  = *q0p0, hi  = *q0p1;
        float4 lo2 = *q1p0, hi2 = *q1p1;
        float4 z = make_float4(0.f, 0.f, 0.f, 0.f);
        *q0p0 = z; *q0p1 = z; *q1p0 = z; *q1p1 = z;   // restore invariant

        float bias = fmaf(__ldg(&eps_b[s]), __expf(__ldg(&b_log_var[s])),
                          __ldg(&b_mean[s]));
        out[0 * SIZE2 + s] = lo.x + lo2.x + bias;
        out[1 * SIZE2 + s] = lo.y + lo2.y + bias;
        out[2 * SIZE2 + s] = lo.z + lo2.z + bias;
        out[3 * SIZE2 + s] = lo.w + lo2.w + bias;
        out[4 * SIZE2 + s] = hi.x + hi2.x + bias;
        out[5 * SIZE2 + s] = hi.y + hi2.y + bias;
        out[6 * SIZE2 + s] = hi.z + hi2.z + bias;
        out[7 * SIZE2 + s] = hi.w + hi2.w + bias;
    } else {
        int k = BATCH * SIZE2 + (idx - SIZE2);
        if (k < out_size) out[k] = 0.0f;   // kl = 0
    }
}

extern "C" void kernel_launch(void* const* d_in, const int* in_sizes, int n_in,
                              void* d_out, int out_size) {
    const float* x      = (const float*)d_in[0];
    const float* w_mean = (const float*)d_in[1];
    const float* w_lv   = (const float*)d_in[2];
    const float* b_mean = (const float*)d_in[3];
    const float* b_lv   = (const float*)d_in[4];
    const float* eps_w  = (const float*)d_in[5];
    const float* eps_b  = (const float*)d_in[6];
    const int*   rows   = (const int*)d_in[7];
    const int*   cols   = (const int*)d_in[8];
    float* out = (float*)d_out;

    prep_kernel<<<(SIZE1 * 2 + 255) / 256, 256>>>(x);

    spmm_edge_kernel<<<(NUM_EDGES / 8 * 32 + 255) / 256, 256>>>(
        (const float4*)w_mean, (const float4*)w_lv, (const float4*)eps_w,
        rows, cols);

    int fin_n = SIZE2 + 512;                           // nodes + kl tail
    finalize_kernel<<<(fin_n + 255) / 256, 256>>>(b_mean, b_lv, eps_b, out, out_size);
}